// round 6
// baseline (speedup 1.0000x reference)
#include <cuda_runtime.h>
#include <cuda_fp16.h>
#include <cstdint>

#define M_TOT 8192   // B*S
#define N_TOT 4096   // OUT
#define K_TOT 4096   // IN

// ---------------------------------------------------------------------------
// Scratch (device globals)
//  g_xh : fp16(x)                                    [M, K]
//  g_w  : fp16( (nib-8) + ortho/scale )              [N, K]
//  out  = (g_xh . g_w^T) * scale[n]
//  Note: 95% of g_w entries are exact small integers in fp16; x rounding
//  (2^-12 rms) dominates the error -> predicted rel_err ~2e-4.
// ---------------------------------------------------------------------------
static __device__ __half g_xh[(size_t)M_TOT * K_TOT];
static __device__ __half g_w[(size_t)N_TOT * K_TOT];

// ---------------------------------------------------------------------------
// Prep 1: x fp32 -> fp16. One thread: 8 floats.
// ---------------------------------------------------------------------------
__global__ void prep_x(const float* __restrict__ x) {
    size_t i = (size_t)blockIdx.x * blockDim.x + threadIdx.x;
    if (i >= ((size_t)M_TOT * K_TOT) / 8) return;
    const float4* xv = reinterpret_cast<const float4*>(x);
    float4 a = xv[i * 2 + 0];
    float4 b = xv[i * 2 + 1];
    float f[8] = {a.x, a.y, a.z, a.w, b.x, b.y, b.z, b.w};
    uint32_t w[4];
#pragma unroll
    for (int q = 0; q < 4; q++) {
        __half h0 = __float2half_rn(f[2 * q + 0]);
        __half h1 = __float2half_rn(f[2 * q + 1]);
        w[q] = (uint32_t)__half_as_ushort(h0) | ((uint32_t)__half_as_ushort(h1) << 16);
    }
    reinterpret_cast<uint4*>(g_xh)[i] = make_uint4(w[0], w[1], w[2], w[3]);
}

// ---------------------------------------------------------------------------
// Prep 2: W = (nib-8) + ortho/scale, fp16. One thread: 4 packed ints = 8 w.
// ---------------------------------------------------------------------------
__global__ void prep_w(const int* __restrict__ packed,
                       const float* __restrict__ scales,
                       const float* __restrict__ ortho) {
    size_t t = (size_t)blockIdx.x * blockDim.x + threadIdx.x;
    if (t >= ((size_t)N_TOT * (K_TOT / 2)) / 4) return;
    int o = (int)(t >> 9);   // 512 groups of 8 weights per output row
    int jj = (int)(t & 511);

    int4 p = reinterpret_cast<const int4*>(packed)[t];
    float inv = 1.0f / __ldg(&scales[o]);
    const float4* orow =
        reinterpret_cast<const float4*>(ortho + (size_t)o * K_TOT + (size_t)jj * 8);
    float4 t0 = orow[0];
    float4 t1 = orow[1];
    float og[8] = {t0.x, t0.y, t0.z, t0.w, t1.x, t1.y, t1.z, t1.w};
    int pv[4] = {p.x, p.y, p.z, p.w};

    uint32_t w[4];
#pragma unroll
    for (int q = 0; q < 4; q++) {
        float w0 = (float)((pv[q] & 0xF) - 8)        + og[2 * q + 0] * inv;
        float w1 = (float)(((pv[q] >> 4) & 0xF) - 8) + og[2 * q + 1] * inv;
        __half h0 = __float2half_rn(w0);
        __half h1 = __float2half_rn(w1);
        w[q] = (uint32_t)__half_as_ushort(h0) | ((uint32_t)__half_as_ushort(h1) << 16);
    }
    reinterpret_cast<uint4*>(g_w)[t] = make_uint4(w[0], w[1], w[2], w[3]);
}

// ---------------------------------------------------------------------------
// Helpers
// ---------------------------------------------------------------------------
__device__ __forceinline__ void cp16(uint32_t dst, const void* src) {
    asm volatile("cp.async.cg.shared.global [%0], [%1], 16;" ::"r"(dst), "l"(src));
}
// 128-row x 128-byte tile, xor swizzle; 256 threads participate.
__device__ __forceinline__ void load_tile(uint32_t tb, const char* src,
                                          size_t stride_b, int c, int r0) {
#pragma unroll
    for (int i = 0; i < 4; i++) {
        int row = r0 + i * 32;
        cp16(tb + row * 128 + (((uint32_t)(c ^ (row & 7))) << 4),
             src + (size_t)row * stride_b + c * 16);
    }
}
// L2-friendly block swizzle: bands of 8 M-blocks x 32 N-blocks.
__device__ __forceinline__ void block_coords(int& bm, int& bn) {
    int gid = blockIdx.x;
    int band = gid >> 8;
    int rem = gid & 255;
    bm = ((band << 3) + (rem & 7)) * 128;
    bn = (rem >> 3) * 128;
}

// ---------------------------------------------------------------------------
// GEMM (fp16 HMMA): out[m][n] = scale[n] * (xh . w^T)
// Tile 128x128, BK=64 fp16 (128B rows), 3-stage cp.async, 8 warps (2x4).
// ---------------------------------------------------------------------------
#define BF_STAGE 32768
__global__ void __launch_bounds__(256, 2)
gemm_f16(float* __restrict__ out, const float* __restrict__ scales) {
    extern __shared__ char smem_raw[];
    uint32_t S = (uint32_t)__cvta_generic_to_shared(smem_raw);
    const int tid = threadIdx.x;
    const int lane = tid & 31;
    const int warp = tid >> 5;
    const int wm = warp >> 2;
    const int wn = warp & 3;
    int bm, bn;
    block_coords(bm, bn);

    const int c = tid & 7;
    const int r0 = tid >> 3;
    const char* Ab = (const char*)(g_xh + (size_t)bm * K_TOT);
    const char* Bb = (const char*)(g_w + (size_t)bn * K_TOT);

    float acc[4][4][4];
#pragma unroll
    for (int a = 0; a < 4; a++)
#pragma unroll
        for (int b = 0; b < 4; b++)
#pragma unroll
            for (int d = 0; d < 4; d++) acc[a][b][d] = 0.0f;

    const int NCH = K_TOT / 64;  // 64
    auto load_stage = [&](int s) {
        uint32_t base = S + (s % 3) * BF_STAGE;
        load_tile(base, Ab + (size_t)s * 128, K_TOT * 2, c, r0);
        load_tile(base + 16384, Bb + (size_t)s * 128, K_TOT * 2, c, r0);
    };
    load_stage(0);
    asm volatile("cp.async.commit_group;");
    load_stage(1);
    asm volatile("cp.async.commit_group;");

    for (int t = 0; t < NCH; ++t) {
        asm volatile("cp.async.wait_group 1;");
        __syncthreads();
        if (t + 2 < NCH) load_stage(t + 2);
        asm volatile("cp.async.commit_group;");

        uint32_t aBase = S + (t % 3) * BF_STAGE;
        uint32_t bBase = aBase + 16384;
#pragma unroll
        for (int ks = 0; ks < 4; ++ks) {
            uint32_t af[4][4];
            uint32_t bfm[4][2];
            const int chunk = ks * 2 + (lane >> 4);
            const int lrow = lane & 15;
#pragma unroll
            for (int mi = 0; mi < 4; mi++) {
                int row = wm * 64 + mi * 16 + lrow;
                uint32_t addr = aBase + row * 128 + (((uint32_t)(chunk ^ (row & 7))) << 4);
                asm volatile(
                    "ldmatrix.sync.aligned.m8n8.x4.shared.b16 {%0,%1,%2,%3}, [%4];"
                    : "=r"(af[mi][0]), "=r"(af[mi][1]), "=r"(af[mi][2]), "=r"(af[mi][3])
                    : "r"(addr));
            }
#pragma unroll
            for (int np = 0; np < 2; np++) {
                int row = wn * 32 + np * 16 + lrow;
                uint32_t addr = bBase + row * 128 + (((uint32_t)(chunk ^ (row & 7))) << 4);
                uint32_t q0, q1, q2, q3;
                asm volatile(
                    "ldmatrix.sync.aligned.m8n8.x4.shared.b16 {%0,%1,%2,%3}, [%4];"
                    : "=r"(q0), "=r"(q1), "=r"(q2), "=r"(q3)
                    : "r"(addr));
                bfm[np * 2 + 0][0] = q0; bfm[np * 2 + 0][1] = q2;
                bfm[np * 2 + 1][0] = q1; bfm[np * 2 + 1][1] = q3;
            }
#pragma unroll
            for (int mi = 0; mi < 4; mi++)
#pragma unroll
                for (int nt = 0; nt < 4; nt++) {
                    asm volatile(
                        "mma.sync.aligned.m16n8k16.row.col.f32.f16.f16.f32 "
                        "{%0,%1,%2,%3}, {%4,%5,%6,%7}, {%8,%9}, {%0,%1,%2,%3};"
                        : "+f"(acc[mi][nt][0]), "+f"(acc[mi][nt][1]),
                          "+f"(acc[mi][nt][2]), "+f"(acc[mi][nt][3])
                        : "r"(af[mi][0]), "r"(af[mi][1]), "r"(af[mi][2]), "r"(af[mi][3]),
                          "r"(bfm[nt][0]), "r"(bfm[nt][1]));
                }
        }
    }

    // epilogue: out = acc * scale[n]
#pragma unroll
    for (int nt = 0; nt < 4; nt++) {
        int col = bn + wn * 32 + nt * 8 + (lane & 3) * 2;
        float s0 = __ldg(&scales[col]);
        float s1 = __ldg(&scales[col + 1]);
#pragma unroll
        for (int mi = 0; mi < 4; mi++) {
            int row = bm + wm * 64 + mi * 16 + (lane >> 2);
            float2* p0 = reinterpret_cast<float2*>(out + (size_t)row * N_TOT + col);
            float2* p1 = reinterpret_cast<float2*>(out + (size_t)(row + 8) * N_TOT + col);
            *p0 = make_float2(acc[mi][nt][0] * s0, acc[mi][nt][1] * s1);
            *p1 = make_float2(acc[mi][nt][2] * s0, acc[mi][nt][3] * s1);
        }
    }
}

// ---------------------------------------------------------------------------
// Launch
// ---------------------------------------------------------------------------
extern "C" void kernel_launch(void* const* d_in, const int* in_sizes, int n_in,
                              void* d_out, int out_size) {
    const float* x      = (const float*)d_in[0];
    const int*   packed = (const int*)d_in[1];
    const float* scales = (const float*)d_in[2];
    const float* ortho  = (const float*)d_in[3];
    float* out = (float*)d_out;

    prep_x<<<((size_t)M_TOT * K_TOT / 8 + 255) / 256, 256>>>(x);
    prep_w<<<((size_t)N_TOT * (K_TOT / 2) / 4 + 255) / 256, 256>>>(packed, scales, ortho);

    cudaFuncSetAttribute(gemm_f16, cudaFuncAttributeMaxDynamicSharedMemorySize,
                         3 * BF_STAGE);
    gemm_f16<<<(M_TOT / 128) * (N_TOT / 128), 256, 3 * BF_STAGE>>>(out, scales);
}